// round 13
// baseline (speedup 1.0000x reference)
#include <cuda_runtime.h>
#include <cuda_bf16.h>
#include <stdint.h>
#include <math.h>

// MultiHeadedAttention_11562051961106
// B=2, S=4096, D=512, H=8, DK=64. fp32 in/out. Causal (mask input ignored).
//
// sm_100 baseline ISA. Tensor path = mma.sync bf16 + ldmatrix + cp.async.
//
// Stage 1: q/k/v proj -> HMMA split-bf16 GEMM (128m x 128n tiles), epilogue
//          writes hi/lo bf16 (Q pre-scaled 1/8) in [B,H,S,DK].
// Stage 2: flash attention, HMMA 3-term split-bf16 QK/PV, register softmax,
//          cp.async double-buffered K/V pipeline.
// Stage 3: out = attn @ Wo^T + bo -> HMMA split-bf16 GEMM (fp32 out).

#define B_  2
#define S_  4096
#define D_  512
#define H_  8
#define DK_ 64
#define M_  (B_*S_)

// Scratch (device globals; no allocation allowed)
__device__ __nv_bfloat16 g_qh[(size_t)B_*H_*S_*DK_];
__device__ __nv_bfloat16 g_ql[(size_t)B_*H_*S_*DK_];
__device__ __nv_bfloat16 g_kh[(size_t)B_*H_*S_*DK_];
__device__ __nv_bfloat16 g_kl[(size_t)B_*H_*S_*DK_];
__device__ __nv_bfloat16 g_vh[(size_t)B_*H_*S_*DK_];
__device__ __nv_bfloat16 g_vl[(size_t)B_*H_*S_*DK_];
__device__ float g_attn[(size_t)M_*D_];

// ---- helpers ----------------------------------------------------------------
__device__ __forceinline__ uint32_t smem_u32(const void* p) {
    uint32_t a;
    asm("{ .reg .u64 t; cvta.to.shared.u64 t, %1; cvt.u32.u64 %0, t; }"
        : "=r"(a) : "l"(p));
    return a;
}
__device__ __forceinline__ void ldsm_x4(uint32_t& r0, uint32_t& r1,
                                        uint32_t& r2, uint32_t& r3, uint32_t addr) {
    asm volatile("ldmatrix.sync.aligned.m8n8.x4.shared.b16 {%0,%1,%2,%3}, [%4];"
                 : "=r"(r0), "=r"(r1), "=r"(r2), "=r"(r3) : "r"(addr));
}
__device__ __forceinline__ void ldsm_x4_t(uint32_t& r0, uint32_t& r1,
                                          uint32_t& r2, uint32_t& r3, uint32_t addr) {
    asm volatile("ldmatrix.sync.aligned.m8n8.x4.trans.shared.b16 {%0,%1,%2,%3}, [%4];"
                 : "=r"(r0), "=r"(r1), "=r"(r2), "=r"(r3) : "r"(addr));
}
__device__ __forceinline__ void mma_bf16(float& c0, float& c1, float& c2, float& c3,
                                         uint32_t a0, uint32_t a1, uint32_t a2, uint32_t a3,
                                         uint32_t b0, uint32_t b1) {
    asm volatile(
        "mma.sync.aligned.m16n8k16.row.col.f32.bf16.bf16.f32 "
        "{%0,%1,%2,%3}, {%4,%5,%6,%7}, {%8,%9}, {%0,%1,%2,%3};"
        : "+f"(c0), "+f"(c1), "+f"(c2), "+f"(c3)
        : "r"(a0), "r"(a1), "r"(a2), "r"(a3), "r"(b0), "r"(b1));
}
__device__ __forceinline__ uint32_t bf16x2_of(float a, float b) {
    __nv_bfloat162 v = __halves2bfloat162(__float2bfloat16(a), __float2bfloat16(b));
    return *reinterpret_cast<uint32_t*>(&v);
}
__device__ __forceinline__ void split_pack(float a, float b, uint32_t& hi, uint32_t& lo) {
    const __nv_bfloat16 ha = __float2bfloat16(a), hb = __float2bfloat16(b);
    const float ra = a - __bfloat162float(ha);
    const float rb = b - __bfloat162float(hb);
    const __nv_bfloat162 Hv = __halves2bfloat162(ha, hb);
    hi = *reinterpret_cast<const uint32_t*>(&Hv);
    lo = bf16x2_of(ra, rb);
}
__device__ __forceinline__ void cp_async16(uint32_t saddr, const void* gaddr) {
    asm volatile("cp.async.cg.shared.global [%0], [%1], 16;"
                 :: "r"(saddr), "l"(gaddr) : "memory");
}
#define CP_COMMIT() asm volatile("cp.async.commit_group;" ::: "memory")
#define CP_WAIT0()  asm volatile("cp.async.wait_group 0;" ::: "memory")

// ============================================================================
// HMMA bf16-split GEMM: C = A @ W^T + bias.  Tile 128m x 128n, 256 thr.
// Warps: wm (4, 32 rows) x wn (2, 64 cols).  K slabs of 32.
// MODE 0/1/2: epilogue splits to hi/lo bf16 -> g_{q,k,v}{h,l} (Q scaled 1/8).
// MODE 3: A = g_attn, fp32 out.
// ============================================================================
#define PITCH 40   // bf16 per smem row (80B)

template<int MODE>
__global__ void __launch_bounds__(256) gemm_mma_kernel(
    const float* __restrict__ Ain, const float* __restrict__ W,
    const float* __restrict__ bias, float* __restrict__ outp)
{
    __shared__ __align__(16) __nv_bfloat16 Ah[128*PITCH], Al[128*PITCH];
    __shared__ __align__(16) __nv_bfloat16 Wh[128*PITCH], Wl[128*PITCH];

    const float* A = (MODE == 3) ? g_attn : Ain;
    const int t    = threadIdx.x;
    const int lane = t & 31;
    const int wid  = t >> 5;
    const int wm   = wid & 3;
    const int wn   = wid >> 2;
    const int m0   = blockIdx.y * 128;
    const int n0   = blockIdx.x * 128;

    const uint32_t sAh = smem_u32(Ah), sAl = smem_u32(Al);
    const uint32_t sWh = smem_u32(Wh), sWl = smem_u32(Wl);

    const uint32_t aoff = (uint32_t)((wm*32 + (lane & 15)) * PITCH + (lane >> 4) * 8) * 2;
    const uint32_t boff = (uint32_t)((wn*64 + ((lane >> 4) ? 8 : 0) + (lane & 7)) * PITCH
                                     + ((lane >> 3) & 1) * 8) * 2;

    float c[2][8][4];
    #pragma unroll
    for (int i = 0; i < 2; i++)
        #pragma unroll
        for (int j = 0; j < 8; j++)
            #pragma unroll
            for (int k = 0; k < 4; k++) c[i][j][k] = 0.f;

    for (int s = 0; s < 16; s++) {
        const int k0s = s * 32;
        __syncthreads();

        #pragma unroll
        for (int p = 0; p < 4; p++) {
            const int idx = t + p * 256;
            const int row = idx >> 3;
            const int cq  = idx & 7;
            const float4 f = *(const float4*)(A + (size_t)(m0 + row) * D_ + k0s + cq * 4);
            uint32_t h01, l01, h23, l23;
            split_pack(f.x, f.y, h01, l01);
            split_pack(f.z, f.w, h23, l23);
            *(uint2*)&Ah[row * PITCH + cq * 4] = make_uint2(h01, h23);
            *(uint2*)&Al[row * PITCH + cq * 4] = make_uint2(l01, l23);
        }
        #pragma unroll
        for (int p = 0; p < 4; p++) {
            const int idx = t + p * 256;
            const int row = idx >> 3;
            const int cq  = idx & 7;
            const float4 f = *(const float4*)(W + (size_t)(n0 + row) * D_ + k0s + cq * 4);
            uint32_t h01, l01, h23, l23;
            split_pack(f.x, f.y, h01, l01);
            split_pack(f.z, f.w, h23, l23);
            *(uint2*)&Wh[row * PITCH + cq * 4] = make_uint2(h01, h23);
            *(uint2*)&Wl[row * PITCH + cq * 4] = make_uint2(l01, l23);
        }
        __syncthreads();

        #pragma unroll
        for (int ks = 0; ks < 2; ks++) {
            const uint32_t kb = ks * 32;
            uint32_t ah[2][4], al[2][4];
            #pragma unroll
            for (int mt = 0; mt < 2; mt++) {
                ldsm_x4(ah[mt][0], ah[mt][1], ah[mt][2], ah[mt][3],
                        sAh + aoff + mt * (16 * PITCH * 2) + kb);
                ldsm_x4(al[mt][0], al[mt][1], al[mt][2], al[mt][3],
                        sAl + aoff + mt * (16 * PITCH * 2) + kb);
            }
            uint32_t wh[8][2], wl[8][2];
            #pragma unroll
            for (int np = 0; np < 4; np++) {
                uint32_t r0, r1, r2, r3;
                ldsm_x4(r0, r1, r2, r3, sWh + boff + np * (16 * PITCH * 2) + kb);
                wh[2*np][0] = r0; wh[2*np][1] = r1; wh[2*np+1][0] = r2; wh[2*np+1][1] = r3;
                ldsm_x4(r0, r1, r2, r3, sWl + boff + np * (16 * PITCH * 2) + kb);
                wl[2*np][0] = r0; wl[2*np][1] = r1; wl[2*np+1][0] = r2; wl[2*np+1][1] = r3;
            }
            #pragma unroll
            for (int mt = 0; mt < 2; mt++)
                #pragma unroll
                for (int nt = 0; nt < 8; nt++) {
                    float* cc = c[mt][nt];
                    mma_bf16(cc[0], cc[1], cc[2], cc[3],
                             ah[mt][0], ah[mt][1], ah[mt][2], ah[mt][3],
                             wh[nt][0], wh[nt][1]);
                    mma_bf16(cc[0], cc[1], cc[2], cc[3],
                             ah[mt][0], ah[mt][1], ah[mt][2], ah[mt][3],
                             wl[nt][0], wl[nt][1]);
                    mma_bf16(cc[0], cc[1], cc[2], cc[3],
                             al[mt][0], al[mt][1], al[mt][2], al[mt][3],
                             wh[nt][0], wh[nt][1]);
                }
        }
    }

    const int g   = lane >> 2;
    const int tig = lane & 3;
    const float sc = (MODE == 0) ? 0.125f : 1.0f;
    #pragma unroll
    for (int mt = 0; mt < 2; mt++) {
        #pragma unroll
        for (int nt = 0; nt < 8; nt++) {
            const int n = n0 + wn*64 + nt*8 + tig*2;
            const float b0 = bias[n], b1 = bias[n+1];
            #pragma unroll
            for (int half = 0; half < 2; half++) {
                const int m = m0 + wm*32 + mt*16 + g + half*8;
                const float v0 = (c[mt][nt][2*half+0] + b0) * sc;
                const float v1 = (c[mt][nt][2*half+1] + b1) * sc;
                if (MODE < 3) {
                    __nv_bfloat16 *OH, *OL;
                    if      (MODE == 0) { OH = g_qh; OL = g_ql; }
                    else if (MODE == 1) { OH = g_kh; OL = g_kl; }
                    else                { OH = g_vh; OL = g_vl; }
                    const int bb = m >> 12;
                    const int ss = m & (S_ - 1);
                    const int hh = n >> 6;
                    const int dk = n & (DK_ - 1);
                    const size_t idx = ((size_t)((bb*H_ + hh)*S_) + ss)*DK_ + dk;
                    uint32_t hi, lo;
                    split_pack(v0, v1, hi, lo);
                    *(uint32_t*)&OH[idx] = hi;
                    *(uint32_t*)&OL[idx] = lo;
                } else {
                    float* dst = outp + (size_t)m * D_ + n;
                    dst[0] = v0; dst[1] = v1;
                }
            }
        }
    }
}

// ============================================================================
// R13 HMMA flash attention with cp.async double-buffered K/V.
// Grid (B*H, S/128), block 128 (4 warps x 32 q rows). Key tiles of 32.
// SMEM: Qh/Ql [128][72] + 2 x (Kh|Kl|Vh|Vl [32][72]) bf16 = 73728 B.
// ============================================================================
#define PQ 72
#define PK 72
#define KVARR   (32*PK)           // elements per K/V array
#define KVBUF   (4*KVARR)         // elements per double-buffer stage
#define FLASH_SMEM_BYTES ((2*128*PQ + 2*KVBUF) * 2)   // 73728

__global__ void __launch_bounds__(128, 2) flash_mma_kernel()
{
    extern __shared__ __nv_bfloat16 smf[];
    __nv_bfloat16* Qh = smf;
    __nv_bfloat16* Ql = smf + 128*PQ;
    const uint32_t sQh = smem_u32(Qh), sQl = smem_u32(Ql);
    const uint32_t sKV = smem_u32(smf + 2*128*PQ);   // buffer 0 base (bytes)

    const int bh = blockIdx.x;
    const int qt = gridDim.y - 1 - blockIdx.y;     // heavy-first
    const int q0 = qt * 128;
    const int t  = threadIdx.x;
    const int lane = t & 31;
    const int w    = t >> 5;
    const int g    = lane >> 2;
    const int tig  = lane & 3;
    const int wbase = q0 + w*32;

    // ---- stage Q hi/lo (once) ----
    {
        const size_t qi = ((size_t)bh*S_ + q0 + t) * DK_;
        const uint4* srch = (const uint4*)&g_qh[qi];
        const uint4* srcl = (const uint4*)&g_ql[qi];
        #pragma unroll
        for (int c = 0; c < 8; c++) {
            *(uint4*)&Qh[t*PQ + c*8] = srch[c];
            *(uint4*)&Ql[t*PQ + c*8] = srcl[c];
        }
    }

    const uint32_t aoffQ = (uint32_t)((w*32 + (lane & 15)) * PQ + (lane >> 4) * 8) * 2;
    const uint32_t boffK = (uint32_t)((((lane >> 4) ? 8 : 0) + (lane & 7)) * PK
                                      + ((lane >> 3) & 1) * 8) * 2;
    const uint32_t voffV = (uint32_t)(((((lane >> 3) & 1) * 8) + (lane & 7)) * PK
                                      + (lane >> 4) * 8) * 2;

    float m_[2][2], l_[2][2];
    #pragma unroll
    for (int i = 0; i < 2; i++)
        #pragma unroll
        for (int j = 0; j < 2; j++) { m_[i][j] = -1e30f; l_[i][j] = 0.f; }

    float o[2][8][4];
    #pragma unroll
    for (int i = 0; i < 2; i++)
        #pragma unroll
        for (int j = 0; j < 8; j++)
            #pragma unroll
            for (int k = 0; k < 4; k++) o[i][j][k] = 0.f;

    const int r_st  = t >> 2;     // key row 0..31
    const int qd_st = t & 3;      // 16-elem quarter
    const int kend  = q0 + 128;
    const uint32_t so2 = (uint32_t)(r_st*PK + qd_st*16) * 2;   // byte offset in array

    // async stage of tile j0 into buffer b
    auto stage = [&](int j0, int b) {
        const size_t gb = ((size_t)bh*S_ + j0 + r_st) * DK_ + qd_st * 16;
        const uint32_t base = sKV + (uint32_t)b * (KVBUF*2);
        cp_async16(base + 0*KVARR*2 + so2,      &g_kh[gb]);
        cp_async16(base + 0*KVARR*2 + so2 + 16, &g_kh[gb + 8]);
        cp_async16(base + 1*KVARR*2 + so2,      &g_kl[gb]);
        cp_async16(base + 1*KVARR*2 + so2 + 16, &g_kl[gb + 8]);
        cp_async16(base + 2*KVARR*2 + so2,      &g_vh[gb]);
        cp_async16(base + 2*KVARR*2 + so2 + 16, &g_vh[gb + 8]);
        cp_async16(base + 3*KVARR*2 + so2,      &g_vl[gb]);
        cp_async16(base + 3*KVARR*2 + so2 + 16, &g_vl[gb + 8]);
    };

    stage(0, 0);
    CP_COMMIT();

    for (int j0 = 0; j0 < kend; j0 += 32) {
        const int b = (j0 >> 5) & 1;
        CP_WAIT0();        // tile j0 data arrived (this thread's copies)
        __syncthreads();   // all threads' copies visible; prior reads of buf b^1 done

        if (j0 + 32 < kend) { stage(j0 + 32, b ^ 1); CP_COMMIT(); }

        const uint32_t kvb = sKV + (uint32_t)b * (KVBUF*2);
        const uint32_t sKh = kvb, sKl = kvb + KVARR*2;
        const uint32_t sVh = kvb + 2*KVARR*2, sVl = kvb + 3*KVARR*2;

        if (j0 <= wbase) {
            // ---- QK ----
            float c[2][4][4];
            #pragma unroll
            for (int i = 0; i < 2; i++)
                #pragma unroll
                for (int j = 0; j < 4; j++)
                    #pragma unroll
                    for (int k = 0; k < 4; k++) c[i][j][k] = 0.f;

            #pragma unroll
            for (int ks = 0; ks < 4; ks++) {
                const uint32_t kb = ks * 32;
                uint32_t ah[2][4], al[2][4];
                #pragma unroll
                for (int mt = 0; mt < 2; mt++) {
                    ldsm_x4(ah[mt][0], ah[mt][1], ah[mt][2], ah[mt][3],
                            sQh + aoffQ + mt*(16*PQ*2) + kb);
                    ldsm_x4(al[mt][0], al[mt][1], al[mt][2], al[mt][3],
                            sQl + aoffQ + mt*(16*PQ*2) + kb);
                }
                uint32_t kh[4][2], kl[4][2];
                #pragma unroll
                for (int np = 0; np < 2; np++) {
                    uint32_t r0, r1, r2, r3;
                    ldsm_x4(r0, r1, r2, r3, sKh + boffK + np*(16*PK*2) + kb);
                    kh[2*np][0] = r0; kh[2*np][1] = r1; kh[2*np+1][0] = r2; kh[2*np+1][1] = r3;
                    ldsm_x4(r0, r1, r2, r3, sKl + boffK + np*(16*PK*2) + kb);
                    kl[2*np][0] = r0; kl[2*np][1] = r1; kl[2*np+1][0] = r2; kl[2*np+1][1] = r3;
                }
                #pragma unroll
                for (int mt = 0; mt < 2; mt++)
                    #pragma unroll
                    for (int nt = 0; nt < 4; nt++) {
                        float* cc = c[mt][nt];
                        mma_bf16(cc[0], cc[1], cc[2], cc[3],
                                 ah[mt][0], ah[mt][1], ah[mt][2], ah[mt][3],
                                 kh[nt][0], kh[nt][1]);
                        mma_bf16(cc[0], cc[1], cc[2], cc[3],
                                 ah[mt][0], ah[mt][1], ah[mt][2], ah[mt][3],
                                 kl[nt][0], kl[nt][1]);
                        mma_bf16(cc[0], cc[1], cc[2], cc[3],
                                 al[mt][0], al[mt][1], al[mt][2], al[mt][3],
                                 kh[nt][0], kh[nt][1]);
                    }
            }

            if (j0 == wbase) {   // diagonal tile: causal mask
                #pragma unroll
                for (int mt = 0; mt < 2; mt++)
                    #pragma unroll
                    for (int nt = 0; nt < 4; nt++)
                        #pragma unroll
                        for (int h = 0; h < 2; h++) {
                            const int row = mt*16 + g + h*8;
                            const int col = nt*8 + 2*tig;
                            if (col     > row) c[mt][nt][2*h+0] = -1e30f;
                            if (col + 1 > row) c[mt][nt][2*h+1] = -1e30f;
                        }
            }

            // ---- softmax in fragment registers ----
            float cf[2][2];
            #pragma unroll
            for (int mt = 0; mt < 2; mt++)
                #pragma unroll
                for (int h = 0; h < 2; h++) {
                    float r = -1e30f;
                    #pragma unroll
                    for (int nt = 0; nt < 4; nt++)
                        r = fmaxf(r, fmaxf(c[mt][nt][2*h], c[mt][nt][2*h+1]));
                    r = fmaxf(r, __shfl_xor_sync(0xFFFFFFFFu, r, 1));
                    r = fmaxf(r, __shfl_xor_sync(0xFFFFFFFFu, r, 2));
                    const float mn = fmaxf(m_[mt][h], r);
                    cf[mt][h] = __expf(m_[mt][h] - mn);
                    m_[mt][h] = mn;
                    float rs = 0.f;
                    #pragma unroll
                    for (int nt = 0; nt < 4; nt++) {
                        const float p0 = __expf(c[mt][nt][2*h+0] - mn);
                        const float p1 = __expf(c[mt][nt][2*h+1] - mn);
                        c[mt][nt][2*h+0] = p0;
                        c[mt][nt][2*h+1] = p1;
                        rs += p0 + p1;
                    }
                    rs += __shfl_xor_sync(0xFFFFFFFFu, rs, 1);
                    rs += __shfl_xor_sync(0xFFFFFFFFu, rs, 2);
                    l_[mt][h] = l_[mt][h] * cf[mt][h] + rs;
                }

            // ---- P fragments (hi + residual) in regs ----
            uint32_t pa[2][2][4], pl[2][2][4];
            #pragma unroll
            for (int mt = 0; mt < 2; mt++)
                #pragma unroll
                for (int ks2 = 0; ks2 < 2; ks2++) {
                    split_pack(c[mt][2*ks2  ][0], c[mt][2*ks2  ][1], pa[mt][ks2][0], pl[mt][ks2][0]);
                    split_pack(c[mt][2*ks2  ][2], c[mt][2*ks2  ][3], pa[mt][ks2][1], pl[mt][ks2][1]);
                    split_pack(c[mt][2*ks2+1][0], c[mt][2*ks2+1][1], pa[mt][ks2][2], pl[mt][ks2][2]);
                    split_pack(c[mt][2*ks2+1][2], c[mt][2*ks2+1][3], pa[mt][ks2][3], pl[mt][ks2][3]);
                }

            // ---- rescale accumulators ----
            #pragma unroll
            for (int mt = 0; mt < 2; mt++)
                #pragma unroll
                for (int nt8 = 0; nt8 < 8; nt8++) {
                    o[mt][nt8][0] *= cf[mt][0];
                    o[mt][nt8][1] *= cf[mt][0];
                    o[mt][nt8][2] *= cf[mt][1];
                    o[mt][nt8][3] *= cf[mt][1];
                }

            // ---- PV ----
            #pragma unroll
            for (int ks2 = 0; ks2 < 2; ks2++) {
                uint32_t vh[8][2], vl[8][2];
                #pragma unroll
                for (int np = 0; np < 4; np++) {
                    uint32_t r0, r1, r2, r3;
                    ldsm_x4_t(r0, r1, r2, r3, sVh + voffV + ks2*(16*PK*2) + np*32);
                    vh[2*np][0] = r0; vh[2*np][1] = r1; vh[2*np+1][0] = r2; vh[2*np+1][1] = r3;
                    ldsm_x4_t(r0, r1, r2, r3, sVl + voffV + ks2*(16*PK*2) + np*32);
                    vl[2*np][0] = r0; vl[2*np][1] = r1; vl[2*np+1][0] = r2; vl[2*np+1][1] = r3;
                }
                #pragma unroll
                for (int mt = 0; mt < 2; mt++)
                    #pragma unroll
                    for (int nt8 = 0; nt8 < 8; nt8++) {
                        float* oo = o[mt][nt8];
                        mma_bf16(oo[0], oo[1], oo[2], oo[3],
                                 pa[mt][ks2][0], pa[mt][ks2][1], pa[mt][ks2][2], pa[mt][ks2][3],
                                 vh[nt8][0], vh[nt8][1]);
                        mma_bf16(oo[0], oo[1], oo[2], oo[3],
                                 pa[mt][ks2][0], pa[mt][ks2][1], pa[mt][ks2][2], pa[mt][ks2][3],
                                 vl[nt8][0], vl[nt8][1]);
                        mma_bf16(oo[0], oo[1], oo[2], oo[3],
                                 pl[mt][ks2][0], pl[mt][ks2][1], pl[mt][ks2][2], pl[mt][ks2][3],
                                 vh[nt8][0], vh[nt8][1]);
                    }
            }
        }
    }

    // ---- epilogue: O / l -> g_attn[B,S,H*DK] ----
    const int bb = bh >> 3;
    const int hh = bh & 7;
    float inv[2][2];
    #pragma unroll
    for (int mt = 0; mt < 2; mt++)
        #pragma unroll
        for (int h = 0; h < 2; h++) inv[mt][h] = 1.0f / l_[mt][h];

    #pragma unroll
    for (int mt = 0; mt < 2; mt++)
        #pragma unroll
        for (int nt8 = 0; nt8 < 8; nt8++)
            #pragma unroll
            for (int h = 0; h < 2; h++) {
                const int row = q0 + w*32 + mt*16 + g + h*8;
                float2 v;
                v.x = o[mt][nt8][2*h+0] * inv[mt][h];
                v.y = o[mt][nt8][2*h+1] * inv[mt][h];
                *(float2*)&g_attn[(size_t)(bb*S_ + row)*D_ + hh*DK_ + nt8*8 + 2*tig] = v;
            }
}

// ---------------------------------------------------------------------------
// Inputs: query, key, value, Wq, bq, Wk, bk, Wv, bv, Wo, bo, mask
// ---------------------------------------------------------------------------
extern "C" void kernel_launch(void* const* d_in, const int* in_sizes, int n_in,
                              void* d_out, int out_size)
{
    const float* query = (const float*)d_in[0];
    const float* key   = (const float*)d_in[1];
    const float* value = (const float*)d_in[2];
    const float* Wq    = (const float*)d_in[3];
    const float* bq    = (const float*)d_in[4];
    const float* Wk    = (const float*)d_in[5];
    const float* bk    = (const float*)d_in[6];
    const float* Wv    = (const float*)d_in[7];
    const float* bv    = (const float*)d_in[8];
    const float* Wo    = (const float*)d_in[9];
    const float* bo    = (const float*)d_in[10];
    float* out = (float*)d_out;

    const dim3 ggrid(D_/128, M_/128);   // (4, 64)
    gemm_mma_kernel<0><<<ggrid, 256>>>(query, Wq, bq, nullptr);
    gemm_mma_kernel<1><<<ggrid, 256>>>(key,   Wk, bk, nullptr);
    gemm_mma_kernel<2><<<ggrid, 256>>>(value, Wv, bv, nullptr);

    cudaFuncSetAttribute(flash_mma_kernel,
                         cudaFuncAttributeMaxDynamicSharedMemorySize, FLASH_SMEM_BYTES);
    const dim3 fgrid(B_*H_, S_/128);  // (16, 32)
    flash_mma_kernel<<<fgrid, 128, FLASH_SMEM_BYTES>>>();

    gemm_mma_kernel<3><<<ggrid, 256>>>(nullptr, Wo, bo, out);
}